// round 5
// baseline (speedup 1.0000x reference)
#include <cuda_runtime.h>
#include <cuda_bf16.h>
#include <math.h>
#include <stdint.h>

// Problem constants
#define S_TOK 4096
#define DIM   1024
#define NEXP  8
#define HID   4096
#define NSCORES (NEXP * S_TOK)

// ---------------- device scratch ----------------
__device__ float g_scores[NSCORES];
__device__ float g_thresh;
__device__ int   g_cnt[NEXP];
__device__ int   g_rows[NEXP * S_TOK];
__device__ float g_w[NEXP * S_TOK];
__device__ int   g_pos[NSCORES];
__device__ float g_hidden[(size_t)NEXP * S_TOK * HID];
__device__ float g_y[(size_t)NEXP * S_TOK * DIM];

__global__ void zero_cnt_kernel() {
    if (threadIdx.x < NEXP) g_cnt[threadIdx.x] = 0;
}

// ---------------- router (exact fp32) ----------------
__global__ void router_kernel(const float* __restrict__ x,
                              const float* __restrict__ gw,
                              const float* __restrict__ eb) {
    int s = blockIdx.x;
    int warp = threadIdx.x >> 5, lane = threadIdx.x & 31;
    const float* xs = x + (size_t)s * DIM;
    const float* g  = gw + (size_t)warp * DIM;
    float acc = 0.f;
    for (int i = lane; i < DIM; i += 32) acc += xs[i] * g[i];
    #pragma unroll
    for (int o = 16; o; o >>= 1) acc += __shfl_xor_sync(0xFFFFFFFFu, acc, o);
    __shared__ float l[NEXP];
    if (lane == 0) l[warp] = acc + eb[warp];
    __syncthreads();
    if (threadIdx.x < NEXP) {
        float m = l[0];
        #pragma unroll
        for (int e = 1; e < NEXP; e++) m = fmaxf(m, l[e]);
        float sum = 0.f;
        #pragma unroll
        for (int e = 0; e < NEXP; e++) sum += expf(l[e] - m);
        g_scores[threadIdx.x * S_TOK + s] = expf(l[threadIdx.x] - m) / sum;
    }
}

// ---------------- exact global top-k threshold (radix select) ----------------
__global__ void topk_kernel(const int* __restrict__ cap) {
    __shared__ int hist[256];
    __shared__ unsigned sh_prefix;
    __shared__ int sh_k;
    int k = S_TOK * cap[0];
    if (k < 1) k = 1;
    if (k > NSCORES) k = NSCORES;
    unsigned prefix = 0, mask = 0;
    int kk = k;
    for (int shift = 24; shift >= 0; shift -= 8) {
        for (int i = threadIdx.x; i < 256; i += blockDim.x) hist[i] = 0;
        __syncthreads();
        for (int i = threadIdx.x; i < NSCORES; i += blockDim.x) {
            unsigned u = __float_as_uint(g_scores[i]);
            if ((u & mask) == prefix) atomicAdd(&hist[(u >> shift) & 255], 1);
        }
        __syncthreads();
        if (threadIdx.x == 0) {
            int rem = kk, b = 255;
            for (; b >= 0; --b) {
                if (rem <= hist[b]) break;
                rem -= hist[b];
            }
            if (b < 0) b = 0;
            sh_prefix = prefix | ((unsigned)b << shift);
            sh_k = rem;
        }
        __syncthreads();
        prefix = sh_prefix;
        kk = sh_k;
        mask |= (0xFFu << shift);
        __syncthreads();
    }
    if (threadIdx.x == 0) g_thresh = __uint_as_float(prefix);
}

__global__ void build_kernel() {
    int i = blockIdx.x * blockDim.x + threadIdx.x;
    if (i >= NSCORES) return;
    float sc = g_scores[i];
    int e = i >> 12;
    int p = -1;
    if (sc >= g_thresh) {
        int r = atomicAdd(&g_cnt[e], 1);
        g_rows[e * S_TOK + r] = i & (S_TOK - 1);
        g_w[e * S_TOK + r]    = sc;
        p = r;
    }
    g_pos[i] = p;
}

// ---------------- tf32 tensor-core GEMM, cp.async 3-stage pipeline ----------------
#define BM 128
#define BN 128
#define BKG 32
#define STAGES 3
#define ASTR 36      // As row stride (floats)
#define BSTR 136     // Bs row stride (floats)
#define A_BYTES (BM * ASTR * 4)                 // 18432
#define B_BYTES (BKG * BSTR * 4)                // 17408
#define STAGE_BYTES (A_BYTES + B_BYTES)         // 35840
#define TOKS_OFF (STAGES * STAGE_BYTES)         // 107520
#define SMEM_TOTAL (TOKS_OFF + BM * 4)          // 108032

#define CP16(dst_s, src_g) \
    asm volatile("cp.async.cg.shared.global [%0], [%1], 16;" :: "r"(dst_s), "l"(src_g) : "memory")
#define CP_COMMIT() asm volatile("cp.async.commit_group;" ::: "memory")
#define CP_WAIT1()  asm volatile("cp.async.wait_group 1;" ::: "memory")

__device__ __forceinline__ unsigned ldcvt(const float* p) {
    unsigned u;
    float f = *p;
    asm("cvt.rna.tf32.f32 %0, %1;" : "=r"(u) : "f"(f));
    return u;
}
__device__ __forceinline__ void mma_tf32(float* c, const unsigned* a, const unsigned* b) {
    asm volatile("mma.sync.aligned.m16n8k8.row.col.f32.tf32.tf32.f32 "
        "{%0,%1,%2,%3}, {%4,%5,%6,%7}, {%8,%9}, {%0,%1,%2,%3};"
        : "+f"(c[0]), "+f"(c[1]), "+f"(c[2]), "+f"(c[3])
        : "r"(a[0]), "r"(a[1]), "r"(a[2]), "r"(a[3]), "r"(b[0]), "r"(b[1]));
}
__device__ __forceinline__ uint32_t smem_u32(const void* p) {
    uint32_t a;
    asm("{ .reg .u64 t; cvta.to.shared.u64 t, %1; cvt.u32.u64 %0, t; }" : "=r"(a) : "l"(p));
    return a;
}

// compute one BKG slice from stage slot
__device__ __forceinline__ void compute_stage(const char* smem, int slot,
                                              int wm, int wn, int gid, int tig,
                                              float acc[4][4][4]) {
    const float* As = (const float*)(smem + (size_t)slot * STAGE_BYTES);
    const float* Bs = (const float*)(smem + (size_t)slot * STAGE_BYTES + A_BYTES);
    #pragma unroll
    for (int ks = 0; ks < 4; ks++) {
        unsigned af[4][4], bf[4][2];
        #pragma unroll
        for (int mt = 0; mt < 4; mt++) {
            int r = wm + mt * 16 + gid;
            const float* a0 = As + (size_t)r * ASTR + ks * 8 + tig;
            af[mt][0] = ldcvt(a0);
            af[mt][1] = ldcvt(a0 + 8 * ASTR);
            af[mt][2] = ldcvt(a0 + 4);
            af[mt][3] = ldcvt(a0 + 8 * ASTR + 4);
        }
        #pragma unroll
        for (int nt = 0; nt < 4; nt++) {
            const float* b0 = Bs + (size_t)(ks * 8 + tig) * BSTR + wn + nt * 8 + gid;
            bf[nt][0] = ldcvt(b0);
            bf[nt][1] = ldcvt(b0 + 4 * BSTR);
        }
        #pragma unroll
        for (int mt = 0; mt < 4; mt++)
            #pragma unroll
            for (int nt = 0; nt < 4; nt++)
                mma_tf32(acc[mt][nt], af[mt], bf[nt]);
    }
}

// GEMM1: g_hidden[e][r][h] = gelu( x[tok[r]] @ w1[e] + b1[e] ),  K=DIM, gathered A
__global__ __launch_bounds__(256)
void gemm1_kernel(const float* __restrict__ x,
                  const float* __restrict__ w1,
                  const float* __restrict__ b1) {
    int e = blockIdx.z;
    int n = g_cnt[e];
    int row0 = blockIdx.y * BM;
    if (row0 >= n) return;
    int col0 = blockIdx.x * BN;
    const float* Bg = w1 + (size_t)e * DIM * HID;
    const int ldb = HID;
    const int KIT = DIM / BKG;

    extern __shared__ char smem[];
    int* toks = (int*)(smem + TOKS_OFF);
    int tid = threadIdx.x;

    if (tid < BM) {
        int mg = row0 + tid;
        if (mg >= n) mg = n - 1;
        toks[tid] = g_rows[e * S_TOK + mg];
    }
    __syncthreads();

    int lane = tid & 31, warp = tid >> 5;
    int gid = lane >> 2, tig = lane & 3;
    int wm = (warp & 1) * 64, wn = (warp >> 1) * 32;

    // staging assignments
    int aR = tid >> 1, aH = (tid & 1) * 16;               // A: row, 16-float half
    const float* aSrc = x + (size_t)toks[aR] * DIM + aH;
    uint32_t aDst = smem_u32(smem) + (uint32_t)(aR * ASTR + aH) * 4;
    int bR = tid >> 3, bC = (tid & 7) * 4;                // B: k-row, col base
    const float* bSrc = Bg + (size_t)bR * ldb + col0 + bC;
    uint32_t bDst = smem_u32(smem) + A_BYTES + (uint32_t)(bR * BSTR + bC) * 4;

    float acc[4][4][4];
    #pragma unroll
    for (int mt = 0; mt < 4; mt++)
        #pragma unroll
        for (int nt = 0; nt < 4; nt++)
            #pragma unroll
            for (int i = 0; i < 4; i++) acc[mt][nt][i] = 0.f;

    // prologue: stages 0,1
    #pragma unroll
    for (int s = 0; s < STAGES - 1; s++) {
        uint32_t so = (uint32_t)s * STAGE_BYTES;
        int k0 = s * BKG;
        #pragma unroll
        for (int j = 0; j < 4; j++) CP16(aDst + so + j * 16, aSrc + k0 + j * 4);
        #pragma unroll
        for (int j = 0; j < 4; j++) CP16(bDst + so + j * 32 * BSTR * 0 + (uint32_t)(j * 32) * 4,
                                         bSrc + (size_t)k0 * ldb + j * 32);
        CP_COMMIT();
    }

    for (int it = 0; it < KIT; it++) {
        CP_WAIT1();
        __syncthreads();
        int nxt = it + STAGES - 1;
        if (nxt < KIT) {
            uint32_t so = (uint32_t)(nxt % STAGES) * STAGE_BYTES;
            int k0 = nxt * BKG;
            #pragma unroll
            for (int j = 0; j < 4; j++) CP16(aDst + so + j * 16, aSrc + k0 + j * 4);
            #pragma unroll
            for (int j = 0; j < 4; j++) CP16(bDst + so + (uint32_t)(j * 32) * 4,
                                             bSrc + (size_t)k0 * ldb + j * 32);
        }
        CP_COMMIT();
        compute_stage(smem, it % STAGES, wm, wn, gid, tig, acc);
    }

    const float* b1e = b1 + (size_t)e * HID;
    float* Hb = g_hidden + (size_t)e * S_TOK * HID;
    #pragma unroll
    for (int mt = 0; mt < 4; mt++) {
        #pragma unroll
        for (int half = 0; half < 2; half++) {
            int r = row0 + wm + mt * 16 + gid + half * 8;
            if (r >= n) continue;
            #pragma unroll
            for (int nt = 0; nt < 4; nt++) {
                int c = col0 + wn + nt * 8 + 2 * tig;
                float v0 = acc[mt][nt][half * 2 + 0] + b1e[c];
                float v1 = acc[mt][nt][half * 2 + 1] + b1e[c + 1];
                float t0 = tanhf(0.7978845608028654f * (v0 + 0.044715f * v0 * v0 * v0));
                float t1 = tanhf(0.7978845608028654f * (v1 + 0.044715f * v1 * v1 * v1));
                float2 o;
                o.x = 0.5f * v0 * (1.0f + t0);
                o.y = 0.5f * v1 * (1.0f + t1);
                *(float2*)&Hb[(size_t)r * HID + c] = o;
            }
        }
    }
}

// GEMM2: g_y[e][r][d] = g_w[r] * ( g_hidden[e][r] @ w2[e] + b2[e] ),  K=HID
__global__ __launch_bounds__(256)
void gemm2_kernel(const float* __restrict__ w2,
                  const float* __restrict__ b2) {
    int e = blockIdx.z;
    int n = g_cnt[e];
    int row0 = blockIdx.y * BM;
    if (row0 >= n) return;
    int col0 = blockIdx.x * BN;
    const float* Ag = g_hidden + (size_t)e * S_TOK * HID;
    const float* Bg = w2 + (size_t)e * HID * DIM;
    const int ldb = DIM;
    const int KIT = HID / BKG;

    extern __shared__ char smem[];
    int tid = threadIdx.x;
    int lane = tid & 31, warp = tid >> 5;
    int gid = lane >> 2, tig = lane & 3;
    int wm = (warp & 1) * 64, wn = (warp >> 1) * 32;

    int aR = tid >> 1, aH = (tid & 1) * 16;
    int mg = row0 + aR; if (mg >= n) mg = n - 1;
    const float* aSrc = Ag + (size_t)mg * HID + aH;
    uint32_t aDst = smem_u32(smem) + (uint32_t)(aR * ASTR + aH) * 4;
    int bR = tid >> 3, bC = (tid & 7) * 4;
    const float* bSrc = Bg + (size_t)bR * ldb + col0 + bC;
    uint32_t bDst = smem_u32(smem) + A_BYTES + (uint32_t)(bR * BSTR + bC) * 4;

    float acc[4][4][4];
    #pragma unroll
    for (int mt = 0; mt < 4; mt++)
        #pragma unroll
        for (int nt = 0; nt < 4; nt++)
            #pragma unroll
            for (int i = 0; i < 4; i++) acc[mt][nt][i] = 0.f;

    #pragma unroll
    for (int s = 0; s < STAGES - 1; s++) {
        uint32_t so = (uint32_t)s * STAGE_BYTES;
        int k0 = s * BKG;
        #pragma unroll
        for (int j = 0; j < 4; j++) CP16(aDst + so + j * 16, aSrc + k0 + j * 4);
        #pragma unroll
        for (int j = 0; j < 4; j++) CP16(bDst + so + (uint32_t)(j * 32) * 4,
                                         bSrc + (size_t)k0 * ldb + j * 32);
        CP_COMMIT();
    }

    for (int it = 0; it < KIT; it++) {
        CP_WAIT1();
        __syncthreads();
        int nxt = it + STAGES - 1;
        if (nxt < KIT) {
            uint32_t so = (uint32_t)(nxt % STAGES) * STAGE_BYTES;
            int k0 = nxt * BKG;
            #pragma unroll
            for (int j = 0; j < 4; j++) CP16(aDst + so + j * 16, aSrc + k0 + j * 4);
            #pragma unroll
            for (int j = 0; j < 4; j++) CP16(bDst + so + (uint32_t)(j * 32) * 4,
                                             bSrc + (size_t)k0 * ldb + j * 32);
        }
        CP_COMMIT();
        compute_stage(smem, it % STAGES, wm, wn, gid, tig, acc);
    }

    const float* b2e = b2 + (size_t)e * DIM;
    #pragma unroll
    for (int mt = 0; mt < 4; mt++) {
        #pragma unroll
        for (int half = 0; half < 2; half++) {
            int r = row0 + wm + mt * 16 + gid + half * 8;
            if (r >= n) continue;
            float wg = g_w[e * S_TOK + r];
            #pragma unroll
            for (int nt = 0; nt < 4; nt++) {
                int c = col0 + wn + nt * 8 + 2 * tig;
                float2 o;
                o.x = wg * (acc[mt][nt][half * 2 + 0] + b2e[c]);
                o.y = wg * (acc[mt][nt][half * 2 + 1] + b2e[c + 1]);
                *(float2*)&g_y[((size_t)e * S_TOK + r) * DIM + c] = o;
            }
        }
    }
}

// ---------------- deterministic combine ----------------
__global__ void combine_kernel(float* __restrict__ out) {
    int s = blockIdx.y;
    int d = blockIdx.x * blockDim.x + threadIdx.x;
    float acc = 0.f;
    #pragma unroll
    for (int e = 0; e < NEXP; e++) {
        int p = g_pos[e * S_TOK + s];
        if (p >= 0) acc += g_y[((size_t)(e * S_TOK + p)) * DIM + d];
    }
    out[(size_t)s * DIM + d] = acc;
}

// ---------------- launch ----------------
extern "C" void kernel_launch(void* const* d_in, const int* in_sizes, int n_in,
                              void* d_out, int out_size) {
    const float* x  = (const float*)d_in[0];
    const float* gw = (const float*)d_in[1];
    const float* eb = (const float*)d_in[2];
    const float* w1 = (const float*)d_in[3];
    const float* b1 = (const float*)d_in[4];
    const float* w2 = (const float*)d_in[5];
    const float* b2 = (const float*)d_in[6];
    const int*  cap = (const int*)d_in[7];
    float* out = (float*)d_out;

    static int attr_done = 0;
    if (!attr_done) {
        cudaFuncSetAttribute(gemm1_kernel, cudaFuncAttributeMaxDynamicSharedMemorySize, SMEM_TOTAL);
        cudaFuncSetAttribute(gemm2_kernel, cudaFuncAttributeMaxDynamicSharedMemorySize, SMEM_TOTAL);
        attr_done = 1;
    }

    zero_cnt_kernel<<<1, 32>>>();
    router_kernel<<<S_TOK, 256>>>(x, gw, eb);
    topk_kernel<<<1, 256>>>(cap);
    build_kernel<<<NSCORES / 256, 256>>>();
    gemm1_kernel<<<dim3(HID / BN, S_TOK / BM, NEXP), 256, SMEM_TOTAL>>>(x, w1, b1);
    gemm2_kernel<<<dim3(DIM / BN, S_TOK / BM, NEXP), 256, SMEM_TOTAL>>>(w2, b2);
    combine_kernel<<<dim3(DIM / 256, S_TOK), 256>>>(out);
}